// round 16
// baseline (speedup 1.0000x reference)
#include <cuda_runtime.h>
#include <cstdint>
#include <cstddef>

// CrossLevelAttention via tf32 mma.sync flash attention.
// CTA: 128 threads / 4 warps, BM=128 q rows (32/warp: two 16-row A-tiles),
// BN=64 key tiles, cp.async double-buffered K/V (raw fp32, MMA truncates).
// Every K/V B-fragment feeds BOTH row tiles (halves smem traffic per row).
// V rows PERMUTED within 8-key groups (sigma(n)=(n&1)*4+(n>>1)) so S
// C-layout registers are directly the PV A-fragment — no shuffles.
// PV software-pipelined one slice behind S. exp via ex2 (log2e folded in Q).
// Per-level output accumulated into gmem (RMW).

#define NHEAD 16
#define DH 64
#define CDIM (NHEAD * DH)
#define BM 128
#define BN 64
#define KSK 68            // K tile row stride (floats)
#define KSV 72            // V tile row stride (floats)
#define SCALE_L2E 0.18033688011112042592f   // 0.125 * log2(e)
#define KFLO (BN * KSK)
#define VFLO (BN * KSV)

__device__ __forceinline__ uint32_t f2tf(float f) {
    uint32_t r;
    asm("cvt.rna.tf32.f32 %0, %1;" : "=r"(r) : "f"(f));
    return r;
}

__device__ __forceinline__ float ex2f(float x) {
    float y;
    asm("ex2.approx.f32 %0, %1;" : "=f"(y) : "f"(x));
    return y;
}

__device__ __forceinline__ void mma_tf32(
    float& c0, float& c1, float& c2, float& c3,
    uint32_t a0, uint32_t a1, uint32_t a2, uint32_t a3,
    uint32_t b0, uint32_t b1)
{
    asm volatile(
        "mma.sync.aligned.m16n8k8.row.col.f32.tf32.tf32.f32 "
        "{%0,%1,%2,%3}, {%4,%5,%6,%7}, {%8,%9}, {%0,%1,%2,%3};"
        : "+f"(c0), "+f"(c1), "+f"(c2), "+f"(c3)
        : "r"(a0), "r"(a1), "r"(a2), "r"(a3), "r"(b0), "r"(b1));
}

__device__ __forceinline__ void ldsm4(
    uint32_t& r0, uint32_t& r1, uint32_t& r2, uint32_t& r3, uint32_t saddr)
{
    asm volatile("ldmatrix.sync.aligned.m8n8.x4.shared.b16 {%0,%1,%2,%3}, [%4];"
                 : "=r"(r0), "=r"(r1), "=r"(r2), "=r"(r3) : "r"(saddr));
}

__device__ __forceinline__ void cpasync16(void* sdst, const void* gsrc) {
    uint32_t s = (uint32_t)__cvta_generic_to_shared(sdst);
    asm volatile("cp.async.cg.shared.global [%0], [%1], 16;" :: "r"(s), "l"(gsrc));
}
#define CP_COMMIT() asm volatile("cp.async.commit_group;" ::: "memory")

__device__ __forceinline__ void prefetch_tile(
    const float* __restrict__ kb, const float* __restrict__ vb,
    int kt, float* sK, float* sV, int tid)
{
    #pragma unroll
    for (int it = 0; it < 8; it++) {
        int idx = it * 128 + tid;   // 1024 float4 slots
        int row = idx >> 4;
        int c4  = idx & 15;
        cpasync16(sK + row * KSK + c4 * 4, kb + (size_t)(kt + row) * CDIM + c4 * 4);
        // V: permute rows within each 8-key group: sigma(n) = (n&1)*4 + (n>>1)
        int vrow = (row & ~7) | (((row & 1) << 2) | ((row & 7) >> 1));
        cpasync16(sV + vrow * KSV + c4 * 4, vb + (size_t)(kt + row) * CDIM + c4 * 4);
    }
}

// One level for this warp's 32 q rows; writes (FIRST) / RMW-adds into out.
template <bool CAUSAL, bool FIRST>
__device__ __forceinline__ void attend_level(
    const float* __restrict__ kbase, const float* __restrict__ vbase,
    int n_keys, int qw0 /* warp's first q row */, int ln, int g, int c, int tid,
    const uint32_t (&qf)[8][8], float lw,
    float* sKd, float* sVd, uint32_t kOff, float* __restrict__ outp)
{
    float o0[32], o1[32];
    #pragma unroll
    for (int i = 0; i < 32; i++) { o0[i] = 0.f; o1[i] = 0.f; }
    float rs0 = 0.f, rs1 = 0.f, rs2 = 0.f, rs3 = 0.f;
    const int r0 = qw0 + g;               // rows r0, +8, +16, +24
    const int ntile = n_keys / BN;

    const uint32_t kShared0 = (uint32_t)__cvta_generic_to_shared(sKd) + kOff;

    prefetch_tile(kbase, vbase, 0, sKd, sVd, tid);
    CP_COMMIT();

    for (int t = 0; t < ntile; t++) {
        if (t + 1 < ntile) {
            prefetch_tile(kbase, vbase, (t + 1) * BN,
                          sKd + ((t + 1) & 1) * KFLO,
                          sVd + ((t + 1) & 1) * VFLO, tid);
            CP_COMMIT();
            asm volatile("cp.async.wait_group 1;" ::: "memory");
        } else {
            asm volatile("cp.async.wait_group 0;" ::: "memory");
        }
        __syncthreads();

        const uint32_t* uV = reinterpret_cast<const uint32_t*>(sVd + (t & 1) * VFLO);
        const uint32_t kSharedT = kShared0 + (uint32_t)((t & 1) * KFLO * 4);
        const int kt = t * BN;
        const bool dom = CAUSAL && (kt + BN > qw0);

        // P A-frags of slice s-1 (tile0: pa0-3, tile1: pa4-7)
        uint32_t pa0 = 0, pa1 = 0, pa2 = 0, pa3 = 0;
        uint32_t pa4 = 0, pa5 = 0, pa6 = 0, pa7 = 0;

        #pragma unroll
        for (int s = 0; s < 8; s++) {
            // ---- K B-frags for slice s via ldmatrix.x4 ----
            uint32_t kb[16];
            const uint32_t sa = kSharedT + (uint32_t)(s * 8 * KSK * 4);
            ldsm4(kb[0],  kb[1],  kb[2],  kb[3],  sa);
            ldsm4(kb[4],  kb[5],  kb[6],  kb[7],  sa + 64);
            ldsm4(kb[8],  kb[9],  kb[10], kb[11], sa + 128);
            ldsm4(kb[12], kb[13], kb[14], kb[15], sa + 192);

            // ---- S slice (s): 4 independent chains (2 per row tile) ----
            float cA0 = 0.f, cA1 = 0.f, cA2 = 0.f, cA3 = 0.f;  // t0, kk 0-3
            float cB0 = 0.f, cB1 = 0.f, cB2 = 0.f, cB3 = 0.f;  // t0, kk 4-7
            float cC0 = 0.f, cC1 = 0.f, cC2 = 0.f, cC3 = 0.f;  // t1, kk 0-3
            float cD0 = 0.f, cD1 = 0.f, cD2 = 0.f, cD3 = 0.f;  // t1, kk 4-7
            #pragma unroll
            for (int kk = 0; kk < 4; kk++) {
                mma_tf32(cA0, cA1, cA2, cA3,
                         qf[kk][0], qf[kk][1], qf[kk][2], qf[kk][3],
                         kb[kk * 2], kb[kk * 2 + 1]);
                mma_tf32(cC0, cC1, cC2, cC3,
                         qf[kk][4], qf[kk][5], qf[kk][6], qf[kk][7],
                         kb[kk * 2], kb[kk * 2 + 1]);
                mma_tf32(cB0, cB1, cB2, cB3,
                         qf[kk + 4][0], qf[kk + 4][1], qf[kk + 4][2], qf[kk + 4][3],
                         kb[8 + kk * 2], kb[8 + kk * 2 + 1]);
                mma_tf32(cD0, cD1, cD2, cD3,
                         qf[kk + 4][4], qf[kk + 4][5], qf[kk + 4][6], qf[kk + 4][7],
                         kb[8 + kk * 2], kb[8 + kk * 2 + 1]);
            }

            // ---- PV for slice s-1 (both row tiles; B-frags shared) ----
            if (s > 0) {
                const int sp = s - 1;
                #pragma unroll
                for (int dt = 0; dt < 8; dt++) {
                    uint32_t b0 = uV[(sp * 8 + c) * KSV + dt * 8 + g];
                    uint32_t b1 = uV[(sp * 8 + c + 4) * KSV + dt * 8 + g];
                    mma_tf32(o0[dt * 4 + 0], o0[dt * 4 + 1],
                             o0[dt * 4 + 2], o0[dt * 4 + 3],
                             pa0, pa1, pa2, pa3, b0, b1);
                    mma_tf32(o1[dt * 4 + 0], o1[dt * 4 + 1],
                             o1[dt * 4 + 2], o1[dt * 4 + 3],
                             pa4, pa5, pa6, pa7, b0, b1);
                }
            }

            // ---- consume S(s): ex2 + causal mask ----
            float s0 = cA0 + cB0, s1 = cA1 + cB1;
            float s2 = cA2 + cB2, s3 = cA3 + cB3;
            float s4 = cC0 + cD0, s5 = cC1 + cD1;
            float s6 = cC2 + cD2, s7 = cC3 + cD3;
            float p0, p1, p2, p3, p4, p5, p6, p7;
            if (dom) {
                int k0 = kt + s * 8 + 2 * c;
                p0 = (k0     > r0     ) ? 0.f : ex2f(s0);
                p1 = (k0 + 1 > r0     ) ? 0.f : ex2f(s1);
                p2 = (k0     > r0 + 8 ) ? 0.f : ex2f(s2);
                p3 = (k0 + 1 > r0 + 8 ) ? 0.f : ex2f(s3);
                p4 = (k0     > r0 + 16) ? 0.f : ex2f(s4);
                p5 = (k0 + 1 > r0 + 16) ? 0.f : ex2f(s5);
                p6 = (k0     > r0 + 24) ? 0.f : ex2f(s6);
                p7 = (k0 + 1 > r0 + 24) ? 0.f : ex2f(s7);
            } else {
                p0 = ex2f(s0); p1 = ex2f(s1); p2 = ex2f(s2); p3 = ex2f(s3);
                p4 = ex2f(s4); p5 = ex2f(s5); p6 = ex2f(s6); p7 = ex2f(s7);
            }
            // RNA-round p to tf32 so rs and MMA see identical values.
            uint32_t u0 = f2tf(p0), u1 = f2tf(p1), u2 = f2tf(p2), u3 = f2tf(p3);
            uint32_t u4 = f2tf(p4), u5 = f2tf(p5), u6 = f2tf(p6), u7 = f2tf(p7);
            rs0 += __uint_as_float(u0) + __uint_as_float(u1);
            rs1 += __uint_as_float(u2) + __uint_as_float(u3);
            rs2 += __uint_as_float(u4) + __uint_as_float(u5);
            rs3 += __uint_as_float(u6) + __uint_as_float(u7);

            // ---- C-layout IS the A-frag under the V row permutation ----
            pa0 = u0; pa1 = u2; pa2 = u1; pa3 = u3;
            pa4 = u4; pa5 = u6; pa6 = u5; pa7 = u7;
        }

        // ---- drain: PV for slice 7 of this tile ----
        #pragma unroll
        for (int dt = 0; dt < 8; dt++) {
            uint32_t b0 = uV[(7 * 8 + c) * KSV + dt * 8 + g];
            uint32_t b1 = uV[(7 * 8 + c + 4) * KSV + dt * 8 + g];
            mma_tf32(o0[dt * 4 + 0], o0[dt * 4 + 1],
                     o0[dt * 4 + 2], o0[dt * 4 + 3],
                     pa0, pa1, pa2, pa3, b0, b1);
            mma_tf32(o1[dt * 4 + 0], o1[dt * 4 + 1],
                     o1[dt * 4 + 2], o1[dt * 4 + 3],
                     pa4, pa5, pa6, pa7, b0, b1);
        }
        __syncthreads();
    }

    // Reduce row sums across the quad.
    rs0 += __shfl_xor_sync(0xffffffffu, rs0, 1);
    rs0 += __shfl_xor_sync(0xffffffffu, rs0, 2);
    rs1 += __shfl_xor_sync(0xffffffffu, rs1, 1);
    rs1 += __shfl_xor_sync(0xffffffffu, rs1, 2);
    rs2 += __shfl_xor_sync(0xffffffffu, rs2, 1);
    rs2 += __shfl_xor_sync(0xffffffffu, rs2, 2);
    rs3 += __shfl_xor_sync(0xffffffffu, rs3, 1);
    rs3 += __shfl_xor_sync(0xffffffffu, rs3, 2);
    float inv0 = lw / rs0, inv1 = lw / rs1, inv2 = lw / rs2, inv3 = lw / rs3;

    #pragma unroll
    for (int dt = 0; dt < 8; dt++) {
        float2* d0 = reinterpret_cast<float2*>(outp + dt * 8 + 2 * c);
        float2* d1 = reinterpret_cast<float2*>(outp + 8  * CDIM + dt * 8 + 2 * c);
        float2* d2 = reinterpret_cast<float2*>(outp + 16 * CDIM + dt * 8 + 2 * c);
        float2* d3 = reinterpret_cast<float2*>(outp + 24 * CDIM + dt * 8 + 2 * c);
        float2 v0 = make_float2(o0[dt * 4 + 0] * inv0, o0[dt * 4 + 1] * inv0);
        float2 v1 = make_float2(o0[dt * 4 + 2] * inv1, o0[dt * 4 + 3] * inv1);
        float2 v2 = make_float2(o1[dt * 4 + 0] * inv2, o1[dt * 4 + 1] * inv2);
        float2 v3 = make_float2(o1[dt * 4 + 2] * inv3, o1[dt * 4 + 3] * inv3);
        if (FIRST) {
            *d0 = v0; *d1 = v1; *d2 = v2; *d3 = v3;
        } else {
            float2 e0 = *d0, e1 = *d1, e2 = *d2, e3 = *d3;
            e0.x += v0.x; e0.y += v0.y; *d0 = e0;
            e1.x += v1.x; e1.y += v1.y; *d1 = e1;
            e2.x += v2.x; e2.y += v2.y; *d2 = e2;
            e3.x += v3.x; e3.y += v3.y; *d3 = e3;
        }
    }
}

__global__ __launch_bounds__(128, 2)
void xlvl_attn_mma_kernel(
    const float* __restrict__ Q,
    const float* __restrict__ K0, const float* __restrict__ V0,
    const float* __restrict__ K1, const float* __restrict__ V1,
    const float* __restrict__ K2, const float* __restrict__ V2,
    const float* __restrict__ logits,
    float* __restrict__ out,
    int T, int T1, int T2)
{
    extern __shared__ __align__(16) float dynsmem[];
    float* sKd = dynsmem;                 // 2 x 64 x 68
    float* sVd = dynsmem + 2 * KFLO;      // 2 x 64 x 72

    const int qb  = (int)(gridDim.x - 1 - blockIdx.x);  // heavy blocks first
    const int h   = blockIdx.y;
    const int b   = blockIdx.z;
    const int tid = threadIdx.x;
    const int w   = tid >> 5;
    const int ln  = tid & 31;
    const int g   = ln >> 2;
    const int c   = ln & 3;
    const int q0  = qb * BM;
    const int qw0 = q0 + w * 32;        // warp's first q row
    const int r0q = qw0 + g;

    // Per-lane ldmatrix byte offset inside a K tile (r7/r15 pairing):
    // matrix m = ln>>3 on rows (ln&7), col offset (m>>1)*8 + (m&1)*4 floats.
    const int lm_m = ln >> 3;
    const int lm_r = ln & 7;
    const uint32_t kOff =
        (uint32_t)((lm_r * KSK + (lm_m >> 1) * 8 + (lm_m & 1) * 4) * 4);

    float l0 = logits[0], l1 = logits[1], l2 = logits[2];
    float mx = fmaxf(l0, fmaxf(l1, l2));
    float e0 = __expf(l0 - mx), e1 = __expf(l1 - mx), e2 = __expf(l2 - mx);
    float winv = 1.0f / (e0 + e1 + e2);
    float w0 = e0 * winv, w1 = e1 * winv, w2 = e2 * winv;

    // Q A-fragments for both 16-row tiles (RNA tf32, SCALE*log2e folded).
    uint32_t qf[8][8];
    {
        const float* qp0 = Q + ((size_t)(b * NHEAD + h) * T + r0q) * DH;
        const float* qp1 = qp0 + 8 * DH;
        const float* qp2 = qp0 + 16 * DH;
        const float* qp3 = qp0 + 24 * DH;
        #pragma unroll
        for (int kk = 0; kk < 8; kk++) {
            qf[kk][0] = f2tf(qp0[kk * 8 + c]     * SCALE_L2E);
            qf[kk][1] = f2tf(qp1[kk * 8 + c]     * SCALE_L2E);
            qf[kk][2] = f2tf(qp0[kk * 8 + c + 4] * SCALE_L2E);
            qf[kk][3] = f2tf(qp1[kk * 8 + c + 4] * SCALE_L2E);
            qf[kk][4] = f2tf(qp2[kk * 8 + c]     * SCALE_L2E);
            qf[kk][5] = f2tf(qp3[kk * 8 + c]     * SCALE_L2E);
            qf[kk][6] = f2tf(qp2[kk * 8 + c + 4] * SCALE_L2E);
            qf[kk][7] = f2tf(qp3[kk * 8 + c + 4] * SCALE_L2E);
        }
    }

    float* outp = out + ((size_t)b * T + r0q) * CDIM + h * DH;

    attend_level<true, true>(K0 + (size_t)b * T  * CDIM + h * DH,
                             V0 + (size_t)b * T  * CDIM + h * DH,
                             q0 + BM, qw0, ln, g, c, tid, qf, w0,
                             sKd, sVd, kOff, outp);
    attend_level<false, false>(K1 + (size_t)b * T1 * CDIM + h * DH,
                               V1 + (size_t)b * T1 * CDIM + h * DH,
                               T1, qw0, ln, g, c, tid, qf, w1,
                               sKd, sVd, kOff, outp);
    attend_level<false, false>(K2 + (size_t)b * T2 * CDIM + h * DH,
                               V2 + (size_t)b * T2 * CDIM + h * DH,
                               T2, qw0, ln, g, c, tid, qf, w2,
                               sKd, sVd, kOff, outp);
}

extern "C" void kernel_launch(void* const* d_in, const int* in_sizes, int n_in,
                              void* d_out, int out_size)
{
    const float* Q      = (const float*)d_in[0];
    const float* K0     = (const float*)d_in[1];
    const float* V0     = (const float*)d_in[2];
    const float* K1     = (const float*)d_in[3];
    const float* V1     = (const float*)d_in[4];
    const float* K2     = (const float*)d_in[5];
    const float* V2     = (const float*)d_in[6];
    const float* logits = (const float*)d_in[7];
    float* out          = (float*)d_out;

    const int B  = 2;
    const int T  = in_sizes[1] / (B * CDIM);
    const int T1 = in_sizes[3] / (B * CDIM);
    const int T2 = in_sizes[5] / (B * CDIM);

    const int smem = (2 * KFLO + 2 * VFLO) * (int)sizeof(float);  // 71,680 B
    static bool configured = false;
    if (!configured) {
        cudaFuncSetAttribute(xlvl_attn_mma_kernel,
                             cudaFuncAttributeMaxDynamicSharedMemorySize, smem);
        configured = true;
    }

    dim3 grid(T / BM, NHEAD, B);
    xlvl_attn_mma_kernel<<<grid, 128, smem>>>(Q, K0, V0, K1, V1, K2, V2, logits,
                                              out, T, T1, T2);
}